// round 2
// baseline (speedup 1.0000x reference)
#include <cuda_runtime.h>
#include <math.h>

#define Dm 128
#define NMAX 50000
#define EMAX 600000

// -------- scratch (device globals; no allocation in kernel_launch) --------
__device__ float g_Q[NMAX * Dm];
__device__ float g_K[NMAX * Dm];
__device__ float g_V[NMAX * Dm];
__device__ float g_Eh[(size_t)EMAX * Dm];
__device__ float g_wV[NMAX * Dm];
__device__ float g_Z[NMAX * 8];
__device__ float g_cs[Dm];
__device__ float g_css[Dm];
__device__ float g_mean[Dm];
__device__ float g_rstd[Dm];

// -------- zero the accumulators (graph replays need fresh zeros) --------
__global__ void k_zero(int N) {
    int i = blockIdx.x * blockDim.x + threadIdx.x;
    if (i < N * Dm) g_wV[i] = 0.0f;
    if (i < N * 8)  g_Z[i]  = 0.0f;
    if (i < Dm) { g_cs[i] = 0.0f; g_css[i] = 0.0f; }
}

// -------- C[M,128] = A[M,128] @ W[128,128], fp32 FFMA, BM=64 BK=64 --------
// which: 0->g_Q, 1->g_K, 2->g_V, 3->g_Eh
__global__ void __launch_bounds__(256) k_gemm128(const float* __restrict__ A,
                                                 const float* __restrict__ W,
                                                 int which, int M) {
    __shared__ float Ws[64 * 128];  // 32 KB  (rows = k chunk, cols = n)
    __shared__ float As[64 * 64];   // 16 KB  (rows = m, cols = k chunk)

    float* C = (which == 0) ? g_Q : (which == 1) ? g_K : (which == 2) ? g_V : g_Eh;

    int tid = threadIdx.x;                 // 256 threads
    long row0 = (long)blockIdx.x * 64;

    int tx = tid & 15;                     // col group: cols tx*8 .. tx*8+7
    int ty = tid >> 4;                     // row group: rows ty*4 .. ty*4+3

    float acc[4][8];
#pragma unroll
    for (int i = 0; i < 4; ++i)
#pragma unroll
        for (int j = 0; j < 8; ++j) acc[i][j] = 0.0f;

    const float4* A4 = (const float4*)A + row0 * 32;   // 32 float4 per row
    float4* Ws4 = (float4*)Ws;
    float4* As4 = (float4*)As;

    for (int kb = 0; kb < 128; kb += 64) {
        // load W chunk: rows kb..kb+63, all 128 cols (contiguous 8192 floats)
        const float4* Wg = (const float4*)(W + kb * 128);
#pragma unroll
        for (int i = 0; i < 8; ++i) Ws4[tid + i * 256] = Wg[tid + i * 256];
        // load A chunk: 64 rows x 64 k (16 float4 per row)
        int kb4 = kb >> 2;
#pragma unroll
        for (int i = 0; i < 4; ++i) {
            int idx = tid + i * 256;
            int r = idx >> 4;
            int j = idx & 15;
            As4[idx] = (row0 + r < M) ? A4[r * 32 + kb4 + j]
                                      : make_float4(0.f, 0.f, 0.f, 0.f);
        }
        __syncthreads();

        const float* Bp = Ws + tx * 8;
        const float* Ap = As + ty * 4 * 64;
#pragma unroll 4
        for (int k = 0; k < 64; ++k) {
            float4 b0 = *(const float4*)(Bp + k * 128);
            float4 b1 = *(const float4*)(Bp + k * 128 + 4);
            float a0 = Ap[k];
            float a1 = Ap[64 + k];
            float a2 = Ap[128 + k];
            float a3 = Ap[192 + k];
            acc[0][0] += a0 * b0.x; acc[0][1] += a0 * b0.y; acc[0][2] += a0 * b0.z; acc[0][3] += a0 * b0.w;
            acc[0][4] += a0 * b1.x; acc[0][5] += a0 * b1.y; acc[0][6] += a0 * b1.z; acc[0][7] += a0 * b1.w;
            acc[1][0] += a1 * b0.x; acc[1][1] += a1 * b0.y; acc[1][2] += a1 * b0.z; acc[1][3] += a1 * b0.w;
            acc[1][4] += a1 * b1.x; acc[1][5] += a1 * b1.y; acc[1][6] += a1 * b1.z; acc[1][7] += a1 * b1.w;
            acc[2][0] += a2 * b0.x; acc[2][1] += a2 * b0.y; acc[2][2] += a2 * b0.z; acc[2][3] += a2 * b0.w;
            acc[2][4] += a2 * b1.x; acc[2][5] += a2 * b1.y; acc[2][6] += a2 * b1.z; acc[2][7] += a2 * b1.w;
            acc[3][0] += a3 * b0.x; acc[3][1] += a3 * b0.y; acc[3][2] += a3 * b0.z; acc[3][3] += a3 * b0.w;
            acc[3][4] += a3 * b1.x; acc[3][5] += a3 * b1.y; acc[3][6] += a3 * b1.z; acc[3][7] += a3 * b1.w;
        }
        __syncthreads();
    }

#pragma unroll
    for (int i = 0; i < 4; ++i) {
        long r = row0 + ty * 4 + i;
        if (r < M) {
            float4* o = (float4*)(C + r * 128 + tx * 8);
            o[0] = make_float4(acc[i][0], acc[i][1], acc[i][2], acc[i][3]);
            o[1] = make_float4(acc[i][4], acc[i][5], acc[i][6], acc[i][7]);
        }
    }
}

// -------- per-edge attention: one warp per edge --------
// lane l covers d = 4l..4l+3; head h = l/4 (dh = 16 => lane quad = one head)
__global__ void __launch_bounds__(256) k_edge(const int* __restrict__ ei, int E) {
    int gw = (blockIdx.x * 256 + threadIdx.x) >> 5;
    if (gw >= E) return;
    int lane = threadIdx.x & 31;
    int s = ei[gw];
    int d = ei[E + gw];

    const float4* q4 = (const float4*)g_Q + (size_t)d * 32;
    const float4* k4 = (const float4*)g_K + (size_t)s * 32;
    const float4* v4 = (const float4*)g_V + (size_t)s * 32;
    const float4* e4 = (const float4*)g_Eh + (size_t)gw * 32;

    float4 qv = q4[lane];
    float4 kv = k4[lane];
    float4 vv = v4[lane];
    float4 ev = e4[lane];

    float p = 0.25f * (qv.x * kv.x * ev.x + qv.y * kv.y * ev.y +
                       qv.z * kv.z * ev.z + qv.w * kv.w * ev.w);
    p += __shfl_xor_sync(0xffffffffu, p, 1);
    p += __shfl_xor_sync(0xffffffffu, p, 2);
    p = fminf(5.0f, fmaxf(-5.0f, p));
    float sc = expf(p);

    float4 m = make_float4(vv.x * sc, vv.y * sc, vv.z * sc, vv.w * sc);
    atomicAdd(((float4*)g_wV) + (size_t)d * 32 + lane, m);   // RED.128 (sm_90+)
    if ((lane & 3) == 0) atomicAdd(&g_Z[d * 8 + (lane >> 2)], sc);
}

// -------- h = x + wV/(Z+eps) -> out (scratch); accumulate column stats --------
__global__ void __launch_bounds__(256) k_resid(const float* __restrict__ x,
                                               float* __restrict__ out, int N) {
    __shared__ float red[256];
    int r0 = blockIdx.x * 64;
    int col = threadIdx.x & 127;
    int rsub = threadIdx.x >> 7;  // 0..1
    int h = col >> 4;

    float s = 0.0f, ss = 0.0f;
#pragma unroll 8
    for (int i = 0; i < 32; ++i) {
        int r = r0 + rsub + i * 2;
        if (r < N) {
            float z = g_Z[r * 8 + h] + 1e-6f;
            size_t idx = (size_t)r * 128 + col;
            float hv = x[idx] + g_wV[idx] / z;
            out[idx] = hv;
            s += hv;
            ss += hv * hv;
        }
    }
    red[threadIdx.x] = s;
    __syncthreads();
    if (threadIdx.x < 128) atomicAdd(&g_cs[col], red[threadIdx.x] + red[threadIdx.x + 128]);
    __syncthreads();
    red[threadIdx.x] = ss;
    __syncthreads();
    if (threadIdx.x < 128) atomicAdd(&g_css[col], red[threadIdx.x] + red[threadIdx.x + 128]);
}

// -------- finalize column statistics --------
__global__ void k_stats(int N) {
    int c = threadIdx.x;
    float inv = 1.0f / (float)N;
    float mean = g_cs[c] * inv;
    float var = g_css[c] * inv - mean * mean;
    g_mean[c] = mean;
    g_rstd[c] = rsqrtf(var + 1e-5f);
}

// -------- apply batchnorm in place on out --------
__global__ void __launch_bounds__(256) k_final(float* __restrict__ out,
                                               const float* __restrict__ gamma,
                                               const float* __restrict__ beta, int N) {
    int i = blockIdx.x * 256 + threadIdx.x;
    if (i < N * Dm) {
        int c = i & 127;
        out[i] = (out[i] - g_mean[c]) * g_rstd[c] * gamma[c] + beta[c];
    }
}

extern "C" void kernel_launch(void* const* d_in, const int* in_sizes, int n_in,
                              void* d_out, int out_size) {
    const float* x     = (const float*)d_in[0];
    const float* eattr = (const float*)d_in[1];
    const float* WQ    = (const float*)d_in[2];
    const float* WK    = (const float*)d_in[3];
    const float* WV    = (const float*)d_in[4];
    const float* WE    = (const float*)d_in[5];
    const float* gamma = (const float*)d_in[6];
    const float* beta  = (const float*)d_in[7];
    const int*   ei    = (const int*)d_in[8];

    int N = in_sizes[0] / Dm;
    int E = in_sizes[1] / Dm;
    float* out = (float*)d_out;

    k_zero<<<(N * Dm + 255) / 256, 256>>>(N);

    k_gemm128<<<(N + 63) / 64, 256>>>(x, WQ, 0, N);
    k_gemm128<<<(N + 63) / 64, 256>>>(x, WK, 1, N);
    k_gemm128<<<(N + 63) / 64, 256>>>(x, WV, 2, N);
    k_gemm128<<<(E + 63) / 64, 256>>>(eattr, WE, 3, E);

    k_edge<<<(E * 32 + 255) / 256, 256>>>(ei, E);

    k_resid<<<(N + 63) / 64, 256>>>(x, out, N);
    k_stats<<<1, 128>>>(N);
    k_final<<<(N * Dm + 255) / 256, 256>>>(out, gamma, beta, N);
}

// round 3
// speedup vs baseline: 1.8491x; 1.8491x over previous
#include <cuda_runtime.h>
#include <math.h>
#include <stdint.h>

#define Dm 128
#define NMAX 50000
#define EMAX 600000

// -------- scratch (device globals; no allocation in kernel_launch) --------
__device__ float g_Q[NMAX * Dm];
__device__ float g_K[NMAX * Dm];
__device__ float g_V[NMAX * Dm];
__device__ float g_Eh[(size_t)EMAX * Dm];
__device__ float g_wV[NMAX * Dm];
__device__ float g_Z[NMAX * 8];
__device__ float g_cs[Dm];
__device__ float g_css[Dm];
__device__ float g_mean[Dm];
__device__ float g_rstd[Dm];

// -------- zero the accumulators (graph replays need fresh zeros) --------
__global__ void k_zero(int N) {
    int i = blockIdx.x * blockDim.x + threadIdx.x;
    if (i < N * Dm) g_wV[i] = 0.0f;
    if (i < N * 8)  g_Z[i]  = 0.0f;
    if (i < Dm) { g_cs[i] = 0.0f; g_css[i] = 0.0f; }
}

// ======================= tf32 tensor-core GEMM =======================
// C[M,128] = A[M,128] @ W[128,128]  (C = g_Eh)
// CTA tile 128x128, 8 warps (4 in M x 2 in N), warp tile 32x64,
// fragments m16n8k8, BK=32 chunks, tf32 rounded (cvt.rna) at smem store.

__device__ __forceinline__ float to_tf32(float x) {
    uint32_t u;
    asm("cvt.rna.tf32.f32 %0, %1;" : "=r"(u) : "f"(x));
    return __uint_as_float(u);
}

__device__ __forceinline__ void mma_tf32(float* c, const uint32_t* a, const uint32_t* b) {
    asm volatile(
        "mma.sync.aligned.m16n8k8.row.col.f32.tf32.tf32.f32 "
        "{%0,%1,%2,%3},{%4,%5,%6,%7},{%8,%9},{%0,%1,%2,%3};"
        : "+f"(c[0]), "+f"(c[1]), "+f"(c[2]), "+f"(c[3])
        : "r"(a[0]), "r"(a[1]), "r"(a[2]), "r"(a[3]), "r"(b[0]), "r"(b[1]));
}

#define AS_STRIDE 36   // 4*r + k distinct mod 32 -> conflict-free A frag loads
#define WS_STRIDE 136  // 8*k + g distinct mod 32 -> conflict-free B frag loads

__global__ void __launch_bounds__(256, 2) k_gemm_tf32(const float* __restrict__ A,
                                                      const float* __restrict__ W,
                                                      int M) {
    __shared__ float As[128 * AS_STRIDE];  // 18.0 KB
    __shared__ float Ws[32 * WS_STRIDE];   // 17.0 KB

    int tid = threadIdx.x;
    int lane = tid & 31;
    int wid = tid >> 5;
    int warp_m = wid & 3;   // 0..3 -> 32-row slab
    int warp_n = wid >> 2;  // 0..1 -> 64-col slab
    int qr = lane >> 2;     // 0..7
    int qc = lane & 3;      // 0..3
    long row0 = (long)blockIdx.x * 128;

    float acc[2][8][4];
#pragma unroll
    for (int mt = 0; mt < 2; ++mt)
#pragma unroll
        for (int nt = 0; nt < 8; ++nt)
#pragma unroll
            for (int i = 0; i < 4; ++i) acc[mt][nt][i] = 0.0f;

    const float4* A4 = (const float4*)A;
    const float4* W4 = (const float4*)W;
    const uint32_t* Asu = (const uint32_t*)As;
    const uint32_t* Wsu = (const uint32_t*)Ws;

    for (int kc = 0; kc < 4; ++kc) {
        int kb = kc * 32;
        __syncthreads();
        // load A chunk: 128 rows x 32 cols (8 float4 per row)
#pragma unroll
        for (int i = 0; i < 4; ++i) {
            int idx = tid + i * 256;
            int r = idx >> 3, c = idx & 7;
            float4 v = (row0 + r < M) ? A4[(row0 + r) * 32 + kc * 8 + c]
                                      : make_float4(0.f, 0.f, 0.f, 0.f);
            v.x = to_tf32(v.x); v.y = to_tf32(v.y);
            v.z = to_tf32(v.z); v.w = to_tf32(v.w);
            *(float4*)&As[r * AS_STRIDE + c * 4] = v;
        }
        // load W chunk: 32 k-rows x 128 cols (32 float4 per row)
#pragma unroll
        for (int i = 0; i < 4; ++i) {
            int idx = tid + i * 256;
            int k = idx >> 5, c = idx & 31;
            float4 v = W4[(kb + k) * 32 + c];
            v.x = to_tf32(v.x); v.y = to_tf32(v.y);
            v.z = to_tf32(v.z); v.w = to_tf32(v.w);
            *(float4*)&Ws[k * WS_STRIDE + c * 4] = v;
        }
        __syncthreads();

#pragma unroll
        for (int ks = 0; ks < 4; ++ks) {
            int k0 = ks * 8;
            uint32_t af[2][4];
#pragma unroll
            for (int mt = 0; mt < 2; ++mt) {
                int rbase = (warp_m * 32 + mt * 16 + qr) * AS_STRIDE;
                af[mt][0] = Asu[rbase + k0 + qc];
                af[mt][1] = Asu[rbase + 8 * AS_STRIDE + k0 + qc];
                af[mt][2] = Asu[rbase + k0 + qc + 4];
                af[mt][3] = Asu[rbase + 8 * AS_STRIDE + k0 + qc + 4];
            }
            uint32_t bf[8][2];
#pragma unroll
            for (int nt = 0; nt < 8; ++nt) {
                int n = warp_n * 64 + nt * 8 + qr;
                bf[nt][0] = Wsu[(k0 + qc) * WS_STRIDE + n];
                bf[nt][1] = Wsu[(k0 + qc + 4) * WS_STRIDE + n];
            }
#pragma unroll
            for (int mt = 0; mt < 2; ++mt)
#pragma unroll
                for (int nt = 0; nt < 8; ++nt)
                    mma_tf32(acc[mt][nt], af[mt], bf[nt]);
        }
    }

    // store C fragments (float2 pairs per half-tile)
#pragma unroll
    for (int mt = 0; mt < 2; ++mt) {
        long r = row0 + warp_m * 32 + mt * 16 + qr;
#pragma unroll
        for (int nt = 0; nt < 8; ++nt) {
            int cc = warp_n * 64 + nt * 8 + 2 * qc;
            if (r < M)
                *(float2*)&g_Eh[r * 128 + cc] = make_float2(acc[mt][nt][0], acc[mt][nt][1]);
            if (r + 8 < M)
                *(float2*)&g_Eh[(r + 8) * 128 + cc] = make_float2(acc[mt][nt][2], acc[mt][nt][3]);
        }
    }
}

// -------- fp32 FFMA GEMM for Q/K/V (exact) --------
__global__ void __launch_bounds__(256) k_gemm128(const float* __restrict__ A,
                                                 const float* __restrict__ W,
                                                 int which, int M) {
    __shared__ float Ws[64 * 128];
    __shared__ float As[64 * 64];

    float* C = (which == 0) ? g_Q : (which == 1) ? g_K : g_V;

    int tid = threadIdx.x;
    long row0 = (long)blockIdx.x * 64;
    int tx = tid & 15;
    int ty = tid >> 4;

    float acc[4][8];
#pragma unroll
    for (int i = 0; i < 4; ++i)
#pragma unroll
        for (int j = 0; j < 8; ++j) acc[i][j] = 0.0f;

    const float4* A4 = (const float4*)A + row0 * 32;
    float4* Ws4 = (float4*)Ws;
    float4* As4 = (float4*)As;

    for (int kb = 0; kb < 128; kb += 64) {
        const float4* Wg = (const float4*)(W + kb * 128);
#pragma unroll
        for (int i = 0; i < 8; ++i) Ws4[tid + i * 256] = Wg[tid + i * 256];
        int kb4 = kb >> 2;
#pragma unroll
        for (int i = 0; i < 4; ++i) {
            int idx = tid + i * 256;
            int r = idx >> 4;
            int j = idx & 15;
            As4[idx] = (row0 + r < M) ? A4[r * 32 + kb4 + j]
                                      : make_float4(0.f, 0.f, 0.f, 0.f);
        }
        __syncthreads();

        const float* Bp = Ws + tx * 8;
        const float* Ap = As + ty * 4 * 64;
#pragma unroll 4
        for (int k = 0; k < 64; ++k) {
            float4 b0 = *(const float4*)(Bp + k * 128);
            float4 b1 = *(const float4*)(Bp + k * 128 + 4);
            float a0 = Ap[k];
            float a1 = Ap[64 + k];
            float a2 = Ap[128 + k];
            float a3 = Ap[192 + k];
            acc[0][0] += a0 * b0.x; acc[0][1] += a0 * b0.y; acc[0][2] += a0 * b0.z; acc[0][3] += a0 * b0.w;
            acc[0][4] += a0 * b1.x; acc[0][5] += a0 * b1.y; acc[0][6] += a0 * b1.z; acc[0][7] += a0 * b1.w;
            acc[1][0] += a1 * b0.x; acc[1][1] += a1 * b0.y; acc[1][2] += a1 * b0.z; acc[1][3] += a1 * b0.w;
            acc[1][4] += a1 * b1.x; acc[1][5] += a1 * b1.y; acc[1][6] += a1 * b1.z; acc[1][7] += a1 * b1.w;
            acc[2][0] += a2 * b0.x; acc[2][1] += a2 * b0.y; acc[2][2] += a2 * b0.z; acc[2][3] += a2 * b0.w;
            acc[2][4] += a2 * b1.x; acc[2][5] += a2 * b1.y; acc[2][6] += a2 * b1.z; acc[2][7] += a2 * b1.w;
            acc[3][0] += a3 * b0.x; acc[3][1] += a3 * b0.y; acc[3][2] += a3 * b0.z; acc[3][3] += a3 * b0.w;
            acc[3][4] += a3 * b1.x; acc[3][5] += a3 * b1.y; acc[3][6] += a3 * b1.z; acc[3][7] += a3 * b1.w;
        }
        __syncthreads();
    }

#pragma unroll
    for (int i = 0; i < 4; ++i) {
        long r = row0 + ty * 4 + i;
        if (r < M) {
            float4* o = (float4*)(C + r * 128 + tx * 8);
            o[0] = make_float4(acc[i][0], acc[i][1], acc[i][2], acc[i][3]);
            o[1] = make_float4(acc[i][4], acc[i][5], acc[i][6], acc[i][7]);
        }
    }
}

// -------- per-edge attention: one warp per edge --------
__global__ void __launch_bounds__(256) k_edge(const int* __restrict__ ei, int E) {
    int gw = (blockIdx.x * 256 + threadIdx.x) >> 5;
    if (gw >= E) return;
    int lane = threadIdx.x & 31;
    int s = ei[gw];
    int d = ei[E + gw];

    const float4* q4 = (const float4*)g_Q + (size_t)d * 32;
    const float4* k4 = (const float4*)g_K + (size_t)s * 32;
    const float4* v4 = (const float4*)g_V + (size_t)s * 32;
    const float4* e4 = (const float4*)g_Eh + (size_t)gw * 32;

    float4 qv = q4[lane];
    float4 kv = k4[lane];
    float4 vv = v4[lane];
    float4 ev = e4[lane];

    float p = 0.25f * (qv.x * kv.x * ev.x + qv.y * kv.y * ev.y +
                       qv.z * kv.z * ev.z + qv.w * kv.w * ev.w);
    p += __shfl_xor_sync(0xffffffffu, p, 1);
    p += __shfl_xor_sync(0xffffffffu, p, 2);
    p = fminf(5.0f, fmaxf(-5.0f, p));
    float sc = expf(p);

    float4 m = make_float4(vv.x * sc, vv.y * sc, vv.z * sc, vv.w * sc);
    atomicAdd(((float4*)g_wV) + (size_t)d * 32 + lane, m);
    if ((lane & 3) == 0) atomicAdd(&g_Z[d * 8 + (lane >> 2)], sc);
}

// -------- h = x + wV/(Z+eps) -> out; accumulate column stats --------
__global__ void __launch_bounds__(256) k_resid(const float* __restrict__ x,
                                               float* __restrict__ out, int N) {
    __shared__ float red[256];
    int r0 = blockIdx.x * 64;
    int col = threadIdx.x & 127;
    int rsub = threadIdx.x >> 7;
    int h = col >> 4;

    float s = 0.0f, ss = 0.0f;
#pragma unroll 8
    for (int i = 0; i < 32; ++i) {
        int r = r0 + rsub + i * 2;
        if (r < N) {
            float z = g_Z[r * 8 + h] + 1e-6f;
            size_t idx = (size_t)r * 128 + col;
            float hv = x[idx] + g_wV[idx] / z;
            out[idx] = hv;
            s += hv;
            ss += hv * hv;
        }
    }
    red[threadIdx.x] = s;
    __syncthreads();
    if (threadIdx.x < 128) atomicAdd(&g_cs[col], red[threadIdx.x] + red[threadIdx.x + 128]);
    __syncthreads();
    red[threadIdx.x] = ss;
    __syncthreads();
    if (threadIdx.x < 128) atomicAdd(&g_css[col], red[threadIdx.x] + red[threadIdx.x + 128]);
}

__global__ void k_stats(int N) {
    int c = threadIdx.x;
    float inv = 1.0f / (float)N;
    float mean = g_cs[c] * inv;
    float var = g_css[c] * inv - mean * mean;
    g_mean[c] = mean;
    g_rstd[c] = rsqrtf(var + 1e-5f);
}

__global__ void __launch_bounds__(256) k_final(float* __restrict__ out,
                                               const float* __restrict__ gamma,
                                               const float* __restrict__ beta, int N) {
    int i = blockIdx.x * 256 + threadIdx.x;
    if (i < N * Dm) {
        int c = i & 127;
        out[i] = (out[i] - g_mean[c]) * g_rstd[c] * gamma[c] + beta[c];
    }
}

extern "C" void kernel_launch(void* const* d_in, const int* in_sizes, int n_in,
                              void* d_out, int out_size) {
    const float* x     = (const float*)d_in[0];
    const float* eattr = (const float*)d_in[1];
    const float* WQ    = (const float*)d_in[2];
    const float* WK    = (const float*)d_in[3];
    const float* WV    = (const float*)d_in[4];
    const float* WE    = (const float*)d_in[5];
    const float* gamma = (const float*)d_in[6];
    const float* beta  = (const float*)d_in[7];
    const int*   ei    = (const int*)d_in[8];

    int N = in_sizes[0] / Dm;
    int E = in_sizes[1] / Dm;
    float* out = (float*)d_out;

    k_zero<<<(N * Dm + 255) / 256, 256>>>(N);

    k_gemm128<<<(N + 63) / 64, 256>>>(x, WQ, 0, N);
    k_gemm128<<<(N + 63) / 64, 256>>>(x, WK, 1, N);
    k_gemm128<<<(N + 63) / 64, 256>>>(x, WV, 2, N);
    k_gemm_tf32<<<(E + 127) / 128, 256>>>(eattr, WE, E);

    k_edge<<<(E * 32 + 255) / 256, 256>>>(ei, E);

    k_resid<<<(N + 63) / 64, 256>>>(x, out, N);
    k_stats<<<1, 128>>>(N);
    k_final<<<(N * Dm + 255) / 256, 256>>>(out, gamma, beta, N);
}

// round 4
// speedup vs baseline: 2.5668x; 1.3881x over previous
#include <cuda_runtime.h>
#include <math.h>
#include <stdint.h>

#define Dm 128
#define NMAX 50000

// -------- scratch (device globals; no allocation in kernel_launch) --------
__device__ float g_Q[NMAX * Dm];
__device__ float g_K[NMAX * Dm];
__device__ float g_V[NMAX * Dm];
__device__ float g_wV[NMAX * Dm];
__device__ float g_Z[NMAX * 8];
__device__ float g_cs[Dm];
__device__ float g_css[Dm];
__device__ float g_mean[Dm];
__device__ float g_rstd[Dm];

__global__ void k_zero(int N) {
    int i = blockIdx.x * blockDim.x + threadIdx.x;
    if (i < N * Dm) g_wV[i] = 0.0f;
    if (i < N * 8)  g_Z[i]  = 0.0f;
    if (i < Dm) { g_cs[i] = 0.0f; g_css[i] = 0.0f; }
}

__device__ __forceinline__ float to_tf32(float x) {
    uint32_t u;
    asm("cvt.rna.tf32.f32 %0, %1;" : "=r"(u) : "f"(x));
    return __uint_as_float(u);
}

__device__ __forceinline__ void mma_tf32(float* c, const uint32_t* a, const uint32_t* b) {
    asm volatile(
        "mma.sync.aligned.m16n8k8.row.col.f32.tf32.tf32.f32 "
        "{%0,%1,%2,%3},{%4,%5,%6,%7},{%8,%9},{%0,%1,%2,%3};"
        : "+f"(c[0]), "+f"(c[1]), "+f"(c[2]), "+f"(c[3])
        : "r"(a[0]), "r"(a[1]), "r"(a[2]), "r"(a[3]), "r"(b[0]), "r"(b[1]));
}

#define AS_STRIDE 36
#define WS_STRIDE 136

// ============ QKV tf32 GEMM: 128x128 CTA tile, blockIdx.y selects matrix ============
__global__ void __launch_bounds__(256, 2) k_gemm_qkv(const float* __restrict__ A,
                                                     const float* __restrict__ WQ,
                                                     const float* __restrict__ WK,
                                                     const float* __restrict__ WV,
                                                     int M) {
    __shared__ float As[128 * AS_STRIDE];
    __shared__ float Ws[32 * WS_STRIDE];

    const float* W = (blockIdx.y == 0) ? WQ : (blockIdx.y == 1) ? WK : WV;
    float* C = (blockIdx.y == 0) ? g_Q : (blockIdx.y == 1) ? g_K : g_V;

    int tid = threadIdx.x;
    int lane = tid & 31;
    int wid = tid >> 5;
    int warp_m = wid & 3;
    int warp_n = wid >> 2;
    int qr = lane >> 2;
    int qc = lane & 3;
    long row0 = (long)blockIdx.x * 128;

    float acc[2][8][4];
#pragma unroll
    for (int mt = 0; mt < 2; ++mt)
#pragma unroll
        for (int nt = 0; nt < 8; ++nt)
#pragma unroll
            for (int i = 0; i < 4; ++i) acc[mt][nt][i] = 0.0f;

    const float4* A4 = (const float4*)A;
    const float4* W4 = (const float4*)W;
    const uint32_t* Asu = (const uint32_t*)As;
    const uint32_t* Wsu = (const uint32_t*)Ws;

    for (int kc = 0; kc < 4; ++kc) {
        __syncthreads();
#pragma unroll
        for (int i = 0; i < 4; ++i) {
            int idx = tid + i * 256;
            int r = idx >> 3, c = idx & 7;
            float4 v = (row0 + r < M) ? A4[(row0 + r) * 32 + kc * 8 + c]
                                      : make_float4(0.f, 0.f, 0.f, 0.f);
            v.x = to_tf32(v.x); v.y = to_tf32(v.y);
            v.z = to_tf32(v.z); v.w = to_tf32(v.w);
            *(float4*)&As[r * AS_STRIDE + c * 4] = v;
        }
#pragma unroll
        for (int i = 0; i < 4; ++i) {
            int idx = tid + i * 256;
            int k = idx >> 5, c = idx & 31;
            float4 v = W4[(kc * 32 + k) * 32 + c];
            v.x = to_tf32(v.x); v.y = to_tf32(v.y);
            v.z = to_tf32(v.z); v.w = to_tf32(v.w);
            *(float4*)&Ws[k * WS_STRIDE + c * 4] = v;
        }
        __syncthreads();

#pragma unroll
        for (int ks = 0; ks < 4; ++ks) {
            int k0 = ks * 8;
            uint32_t af[2][4];
#pragma unroll
            for (int mt = 0; mt < 2; ++mt) {
                int rbase = (warp_m * 32 + mt * 16 + qr) * AS_STRIDE;
                af[mt][0] = Asu[rbase + k0 + qc];
                af[mt][1] = Asu[rbase + 8 * AS_STRIDE + k0 + qc];
                af[mt][2] = Asu[rbase + k0 + qc + 4];
                af[mt][3] = Asu[rbase + 8 * AS_STRIDE + k0 + qc + 4];
            }
            uint32_t bf[8][2];
#pragma unroll
            for (int nt = 0; nt < 8; ++nt) {
                int n = warp_n * 64 + nt * 8 + qr;
                bf[nt][0] = Wsu[(k0 + qc) * WS_STRIDE + n];
                bf[nt][1] = Wsu[(k0 + qc + 4) * WS_STRIDE + n];
            }
#pragma unroll
            for (int mt = 0; mt < 2; ++mt)
#pragma unroll
                for (int nt = 0; nt < 8; ++nt)
                    mma_tf32(acc[mt][nt], af[mt], bf[nt]);
        }
    }

#pragma unroll
    for (int mt = 0; mt < 2; ++mt) {
        long r = row0 + warp_m * 32 + mt * 16 + qr;
#pragma unroll
        for (int nt = 0; nt < 8; ++nt) {
            int cc = warp_n * 64 + nt * 8 + 2 * qc;
            if (r < M)
                *(float2*)&C[r * 128 + cc] = make_float2(acc[mt][nt][0], acc[mt][nt][1]);
            if (r + 8 < M)
                *(float2*)&C[(r + 8) * 128 + cc] = make_float2(acc[mt][nt][2], acc[mt][nt][3]);
        }
    }
}

// ============ Fused Eh GEMM + edge attention ============
// CTA = 64 edges. Phase 1: Eh_tile[64,128] = eattr[rows] @ WE via tf32 mma.
// Phase 2: Eh -> smem (reusing staging), consume per edge: gather Q/K/V,
// score, exp, scatter atomics. Eh never touches global memory.
#define EH_STRIDE 132

__global__ void __launch_bounds__(256) k_eh_edge(const float* __restrict__ A,
                                                 const float* __restrict__ W,
                                                 const int* __restrict__ ei, int E) {
    __shared__ float pool[64 * EH_STRIDE];  // 33.8 KB; unions staging + Eh tile
    float* As = pool;                 // 64*36 = 2304 floats
    float* Ws = pool + 64 * AS_STRIDE;  // 32*136 = 4352 floats (ends at 6656 < 8448)
    float* EhS = pool;                // 64*132, reused after GEMM

    int tid = threadIdx.x;
    int lane = tid & 31;
    int wid = tid >> 5;
    int warp_m = wid & 1;   // 2 slabs of 32 rows
    int warp_n = wid >> 1;  // 4 slabs of 32 cols
    int qr = lane >> 2;
    int qc = lane & 3;
    long row0 = (long)blockIdx.x * 64;

    float acc[2][4][4];
#pragma unroll
    for (int mt = 0; mt < 2; ++mt)
#pragma unroll
        for (int nt = 0; nt < 4; ++nt)
#pragma unroll
            for (int i = 0; i < 4; ++i) acc[mt][nt][i] = 0.0f;

    const float4* A4 = (const float4*)A;
    const float4* W4 = (const float4*)W;
    const uint32_t* Asu = (const uint32_t*)As;
    const uint32_t* Wsu = (const uint32_t*)Ws;

    for (int kc = 0; kc < 4; ++kc) {
        __syncthreads();
        // A chunk: 64 rows x 32 cols = 512 float4, 2 per thread
#pragma unroll
        for (int i = 0; i < 2; ++i) {
            int idx = tid + i * 256;
            int r = idx >> 3, c = idx & 7;
            float4 v = (row0 + r < E) ? A4[(row0 + r) * 32 + kc * 8 + c]
                                      : make_float4(0.f, 0.f, 0.f, 0.f);
            v.x = to_tf32(v.x); v.y = to_tf32(v.y);
            v.z = to_tf32(v.z); v.w = to_tf32(v.w);
            *(float4*)&As[r * AS_STRIDE + c * 4] = v;
        }
        // W chunk: 32 k-rows x 128 cols = 1024 float4, 4 per thread
#pragma unroll
        for (int i = 0; i < 4; ++i) {
            int idx = tid + i * 256;
            int k = idx >> 5, c = idx & 31;
            float4 v = W4[(kc * 32 + k) * 32 + c];
            v.x = to_tf32(v.x); v.y = to_tf32(v.y);
            v.z = to_tf32(v.z); v.w = to_tf32(v.w);
            *(float4*)&Ws[k * WS_STRIDE + c * 4] = v;
        }
        __syncthreads();

#pragma unroll
        for (int ks = 0; ks < 4; ++ks) {
            int k0 = ks * 8;
            uint32_t af[2][4];
#pragma unroll
            for (int mt = 0; mt < 2; ++mt) {
                int rbase = (warp_m * 32 + mt * 16 + qr) * AS_STRIDE;
                af[mt][0] = Asu[rbase + k0 + qc];
                af[mt][1] = Asu[rbase + 8 * AS_STRIDE + k0 + qc];
                af[mt][2] = Asu[rbase + k0 + qc + 4];
                af[mt][3] = Asu[rbase + 8 * AS_STRIDE + k0 + qc + 4];
            }
            uint32_t bf[4][2];
#pragma unroll
            for (int nt = 0; nt < 4; ++nt) {
                int n = warp_n * 32 + nt * 8 + qr;
                bf[nt][0] = Wsu[(k0 + qc) * WS_STRIDE + n];
                bf[nt][1] = Wsu[(k0 + qc + 4) * WS_STRIDE + n];
            }
#pragma unroll
            for (int mt = 0; mt < 2; ++mt)
#pragma unroll
                for (int nt = 0; nt < 4; ++nt)
                    mma_tf32(acc[mt][nt], af[mt], bf[nt]);
        }
    }

    __syncthreads();  // staging dead; safe to overwrite with Eh tile

    // Eh fragments -> smem
#pragma unroll
    for (int mt = 0; mt < 2; ++mt) {
        int r = warp_m * 32 + mt * 16 + qr;
#pragma unroll
        for (int nt = 0; nt < 4; ++nt) {
            int cc = warp_n * 32 + nt * 8 + 2 * qc;
            *(float2*)&EhS[r * EH_STRIDE + cc] = make_float2(acc[mt][nt][0], acc[mt][nt][1]);
            *(float2*)&EhS[(r + 8) * EH_STRIDE + cc] = make_float2(acc[mt][nt][2], acc[mt][nt][3]);
        }
    }
    __syncthreads();

    // ---- edge phase: warp handles 8 edges; lane covers dims 4l..4l+3 ----
#pragma unroll 2
    for (int i = 0; i < 8; ++i) {
        int el = wid * 8 + i;
        long e = row0 + el;
        if (e >= E) break;
        int s = ei[e];
        int d = ei[E + e];

        float4 qv = ((const float4*)g_Q)[(size_t)d * 32 + lane];
        float4 kv = ((const float4*)g_K)[(size_t)s * 32 + lane];
        float4 vv = ((const float4*)g_V)[(size_t)s * 32 + lane];
        float4 ev = *(const float4*)&EhS[el * EH_STRIDE + lane * 4];

        float p = 0.25f * (qv.x * kv.x * ev.x + qv.y * kv.y * ev.y +
                           qv.z * kv.z * ev.z + qv.w * kv.w * ev.w);
        p += __shfl_xor_sync(0xffffffffu, p, 1);
        p += __shfl_xor_sync(0xffffffffu, p, 2);
        p = fminf(5.0f, fmaxf(-5.0f, p));
        float sc = expf(p);

        float4 m = make_float4(vv.x * sc, vv.y * sc, vv.z * sc, vv.w * sc);
        atomicAdd(((float4*)g_wV) + (size_t)d * 32 + lane, m);
        if ((lane & 3) == 0) atomicAdd(&g_Z[d * 8 + (lane >> 2)], sc);
    }
}

// -------- h = x + wV/(Z+eps) -> out; accumulate column stats --------
__global__ void __launch_bounds__(256) k_resid(const float* __restrict__ x,
                                               float* __restrict__ out, int N) {
    __shared__ float red[256];
    int r0 = blockIdx.x * 64;
    int col = threadIdx.x & 127;
    int rsub = threadIdx.x >> 7;
    int h = col >> 4;

    float s = 0.0f, ss = 0.0f;
#pragma unroll 8
    for (int i = 0; i < 32; ++i) {
        int r = r0 + rsub + i * 2;
        if (r < N) {
            float z = g_Z[r * 8 + h] + 1e-6f;
            size_t idx = (size_t)r * 128 + col;
            float hv = x[idx] + g_wV[idx] / z;
            out[idx] = hv;
            s += hv;
            ss += hv * hv;
        }
    }
    red[threadIdx.x] = s;
    __syncthreads();
    if (threadIdx.x < 128) atomicAdd(&g_cs[col], red[threadIdx.x] + red[threadIdx.x + 128]);
    __syncthreads();
    red[threadIdx.x] = ss;
    __syncthreads();
    if (threadIdx.x < 128) atomicAdd(&g_css[col], red[threadIdx.x] + red[threadIdx.x + 128]);
}

__global__ void k_stats(int N) {
    int c = threadIdx.x;
    float inv = 1.0f / (float)N;
    float mean = g_cs[c] * inv;
    float var = g_css[c] * inv - mean * mean;
    g_mean[c] = mean;
    g_rstd[c] = rsqrtf(var + 1e-5f);
}

__global__ void __launch_bounds__(256) k_final(float* __restrict__ out,
                                               const float* __restrict__ gamma,
                                               const float* __restrict__ beta, int N) {
    int i = blockIdx.x * 256 + threadIdx.x;
    if (i < N * Dm) {
        int c = i & 127;
        out[i] = (out[i] - g_mean[c]) * g_rstd[c] * gamma[c] + beta[c];
    }
}

extern "C" void kernel_launch(void* const* d_in, const int* in_sizes, int n_in,
                              void* d_out, int out_size) {
    const float* x     = (const float*)d_in[0];
    const float* eattr = (const float*)d_in[1];
    const float* WQ    = (const float*)d_in[2];
    const float* WK    = (const float*)d_in[3];
    const float* WV    = (const float*)d_in[4];
    const float* WE    = (const float*)d_in[5];
    const float* gamma = (const float*)d_in[6];
    const float* beta  = (const float*)d_in[7];
    const int*   ei    = (const int*)d_in[8];

    int N = in_sizes[0] / Dm;
    int E = in_sizes[1] / Dm;
    float* out = (float*)d_out;

    k_zero<<<(N * Dm + 255) / 256, 256>>>(N);

    dim3 gq((N + 127) / 128, 3);
    k_gemm_qkv<<<gq, 256>>>(x, WQ, WK, WV, N);

    k_eh_edge<<<(E + 63) / 64, 256>>>(eattr, WE, ei, E);

    k_resid<<<(N + 63) / 64, 256>>>(x, out, N);
    k_stats<<<1, 128>>>(N);
    k_final<<<(N * Dm + 255) / 256, 256>>>(out, gamma, beta, N);
}

// round 5
// speedup vs baseline: 2.9982x; 1.1681x over previous
#include <cuda_runtime.h>
#include <math.h>
#include <stdint.h>

#define Dm 128
#define NMAX 50000

// -------- scratch (device globals; no allocation in kernel_launch) --------
__device__ float g_Q[NMAX * Dm];
__device__ float g_KV[(size_t)NMAX * 256];   // K in cols 0..127, V in cols 128..255
__device__ float g_wV[NMAX * Dm];
__device__ float g_Z[NMAX * 8];
__device__ float g_cs[Dm];
__device__ float g_css[Dm];

__global__ void __launch_bounds__(256) k_zero(int N) {
    int i = blockIdx.x * 256 + threadIdx.x;
    if (i < N * 32) ((float4*)g_wV)[i] = make_float4(0.f, 0.f, 0.f, 0.f);
    if (i < N * 2) ((float4*)g_Z)[i] = make_float4(0.f, 0.f, 0.f, 0.f);
    if (i < Dm) { g_cs[i] = 0.0f; g_css[i] = 0.0f; }
}

__device__ __forceinline__ float to_tf32(float x) {
    uint32_t u;
    asm("cvt.rna.tf32.f32 %0, %1;" : "=r"(u) : "f"(x));
    return __uint_as_float(u);
}

__device__ __forceinline__ void mma_tf32(float* c, const uint32_t* a, const uint32_t* b) {
    asm volatile(
        "mma.sync.aligned.m16n8k8.row.col.f32.tf32.tf32.f32 "
        "{%0,%1,%2,%3},{%4,%5,%6,%7},{%8,%9},{%0,%1,%2,%3};"
        : "+f"(c[0]), "+f"(c[1]), "+f"(c[2]), "+f"(c[3])
        : "r"(a[0]), "r"(a[1]), "r"(a[2]), "r"(a[3]), "r"(b[0]), "r"(b[1]));
}

#define AS_STRIDE 36
#define WS_STRIDE 136

// ============ QKV tf32 GEMM: 128x128 CTA tile, blockIdx.y selects matrix ============
__global__ void __launch_bounds__(256, 2) k_gemm_qkv(const float* __restrict__ A,
                                                     const float* __restrict__ WQ,
                                                     const float* __restrict__ WK,
                                                     const float* __restrict__ WV,
                                                     int M) {
    __shared__ float As[128 * AS_STRIDE];
    __shared__ float Ws[32 * WS_STRIDE];

    const float* W = (blockIdx.y == 0) ? WQ : (blockIdx.y == 1) ? WK : WV;
    float* C = (blockIdx.y == 0) ? g_Q : g_KV;
    int cst = (blockIdx.y == 0) ? 128 : 256;           // row stride (floats)
    int coff = (blockIdx.y == 2) ? 128 : 0;            // column offset (V half)

    int tid = threadIdx.x;
    int lane = tid & 31;
    int wid = tid >> 5;
    int warp_m = wid & 3;
    int warp_n = wid >> 2;
    int qr = lane >> 2;
    int qc = lane & 3;
    long row0 = (long)blockIdx.x * 128;

    float acc[2][8][4];
#pragma unroll
    for (int mt = 0; mt < 2; ++mt)
#pragma unroll
        for (int nt = 0; nt < 8; ++nt)
#pragma unroll
            for (int i = 0; i < 4; ++i) acc[mt][nt][i] = 0.0f;

    const float4* A4 = (const float4*)A;
    const float4* W4 = (const float4*)W;
    const uint32_t* Asu = (const uint32_t*)As;
    const uint32_t* Wsu = (const uint32_t*)Ws;

    for (int kc = 0; kc < 4; ++kc) {
        __syncthreads();
#pragma unroll
        for (int i = 0; i < 4; ++i) {
            int idx = tid + i * 256;
            int r = idx >> 3, c = idx & 7;
            float4 v = (row0 + r < M) ? A4[(row0 + r) * 32 + kc * 8 + c]
                                      : make_float4(0.f, 0.f, 0.f, 0.f);
            v.x = to_tf32(v.x); v.y = to_tf32(v.y);
            v.z = to_tf32(v.z); v.w = to_tf32(v.w);
            *(float4*)&As[r * AS_STRIDE + c * 4] = v;
        }
#pragma unroll
        for (int i = 0; i < 4; ++i) {
            int idx = tid + i * 256;
            int k = idx >> 5, c = idx & 31;
            float4 v = W4[(kc * 32 + k) * 32 + c];
            v.x = to_tf32(v.x); v.y = to_tf32(v.y);
            v.z = to_tf32(v.z); v.w = to_tf32(v.w);
            *(float4*)&Ws[k * WS_STRIDE + c * 4] = v;
        }
        __syncthreads();

#pragma unroll
        for (int ks = 0; ks < 4; ++ks) {
            int k0 = ks * 8;
            uint32_t af[2][4];
#pragma unroll
            for (int mt = 0; mt < 2; ++mt) {
                int rbase = (warp_m * 32 + mt * 16 + qr) * AS_STRIDE;
                af[mt][0] = Asu[rbase + k0 + qc];
                af[mt][1] = Asu[rbase + 8 * AS_STRIDE + k0 + qc];
                af[mt][2] = Asu[rbase + k0 + qc + 4];
                af[mt][3] = Asu[rbase + 8 * AS_STRIDE + k0 + qc + 4];
            }
            uint32_t bf[8][2];
#pragma unroll
            for (int nt = 0; nt < 8; ++nt) {
                int n = warp_n * 64 + nt * 8 + qr;
                bf[nt][0] = Wsu[(k0 + qc) * WS_STRIDE + n];
                bf[nt][1] = Wsu[(k0 + qc + 4) * WS_STRIDE + n];
            }
#pragma unroll
            for (int mt = 0; mt < 2; ++mt)
#pragma unroll
                for (int nt = 0; nt < 8; ++nt)
                    mma_tf32(acc[mt][nt], af[mt], bf[nt]);
        }
    }

#pragma unroll
    for (int mt = 0; mt < 2; ++mt) {
        long r = row0 + warp_m * 32 + mt * 16 + qr;
#pragma unroll
        for (int nt = 0; nt < 8; ++nt) {
            int cc = coff + warp_n * 64 + nt * 8 + 2 * qc;
            if (r < M)
                *(float2*)&C[(size_t)r * cst + cc] = make_float2(acc[mt][nt][0], acc[mt][nt][1]);
            if (r + 8 < M)
                *(float2*)&C[(size_t)(r + 8) * cst + cc] = make_float2(acc[mt][nt][2], acc[mt][nt][3]);
        }
    }
}

// ============ Fused Eh GEMM + edge attention ============
#define EH_STRIDE 132

__global__ void __launch_bounds__(256, 3) k_eh_edge(const float* __restrict__ A,
                                                    const float* __restrict__ W,
                                                    const int* __restrict__ ei, int E) {
    __shared__ float pool[64 * EH_STRIDE];  // 33.8 KB; unions staging + Eh tile
    __shared__ int sSrc[64];
    __shared__ int sDst[64];
    float* As = pool;
    float* Ws = pool + 64 * AS_STRIDE;
    float* EhS = pool;

    int tid = threadIdx.x;
    int lane = tid & 31;
    int wid = tid >> 5;
    int warp_m = wid & 1;
    int warp_n = wid >> 1;
    int qr = lane >> 2;
    int qc = lane & 3;
    long row0 = (long)blockIdx.x * 64;

    // preload edge indices (coalesced; consumed after the barrier below)
    if (tid < 64)       sSrc[tid] = (row0 + tid < E) ? ei[row0 + tid] : 0;
    else if (tid < 128) sDst[tid - 64] = (row0 + tid - 64 < E) ? ei[E + row0 + tid - 64] : 0;

    float acc[2][4][4];
#pragma unroll
    for (int mt = 0; mt < 2; ++mt)
#pragma unroll
        for (int nt = 0; nt < 4; ++nt)
#pragma unroll
            for (int i = 0; i < 4; ++i) acc[mt][nt][i] = 0.0f;

    const float4* A4 = (const float4*)A;
    const float4* W4 = (const float4*)W;
    const uint32_t* Asu = (const uint32_t*)As;
    const uint32_t* Wsu = (const uint32_t*)Ws;

    for (int kc = 0; kc < 4; ++kc) {
        __syncthreads();
#pragma unroll
        for (int i = 0; i < 2; ++i) {
            int idx = tid + i * 256;
            int r = idx >> 3, c = idx & 7;
            float4 v = (row0 + r < E) ? A4[(row0 + r) * 32 + kc * 8 + c]
                                      : make_float4(0.f, 0.f, 0.f, 0.f);
            v.x = to_tf32(v.x); v.y = to_tf32(v.y);
            v.z = to_tf32(v.z); v.w = to_tf32(v.w);
            *(float4*)&As[r * AS_STRIDE + c * 4] = v;
        }
#pragma unroll
        for (int i = 0; i < 4; ++i) {
            int idx = tid + i * 256;
            int k = idx >> 5, c = idx & 31;
            float4 v = W4[(kc * 32 + k) * 32 + c];
            v.x = to_tf32(v.x); v.y = to_tf32(v.y);
            v.z = to_tf32(v.z); v.w = to_tf32(v.w);
            *(float4*)&Ws[k * WS_STRIDE + c * 4] = v;
        }
        __syncthreads();

#pragma unroll
        for (int ks = 0; ks < 4; ++ks) {
            int k0 = ks * 8;
            uint32_t af[2][4];
#pragma unroll
            for (int mt = 0; mt < 2; ++mt) {
                int rbase = (warp_m * 32 + mt * 16 + qr) * AS_STRIDE;
                af[mt][0] = Asu[rbase + k0 + qc];
                af[mt][1] = Asu[rbase + 8 * AS_STRIDE + k0 + qc];
                af[mt][2] = Asu[rbase + k0 + qc + 4];
                af[mt][3] = Asu[rbase + 8 * AS_STRIDE + k0 + qc + 4];
            }
            uint32_t bf[4][2];
#pragma unroll
            for (int nt = 0; nt < 4; ++nt) {
                int n = warp_n * 32 + nt * 8 + qr;
                bf[nt][0] = Wsu[(k0 + qc) * WS_STRIDE + n];
                bf[nt][1] = Wsu[(k0 + qc + 4) * WS_STRIDE + n];
            }
#pragma unroll
            for (int mt = 0; mt < 2; ++mt)
#pragma unroll
                for (int nt = 0; nt < 4; ++nt)
                    mma_tf32(acc[mt][nt], af[mt], bf[nt]);
        }
    }

    __syncthreads();  // staging dead; overwrite with Eh tile

#pragma unroll
    for (int mt = 0; mt < 2; ++mt) {
        int r = warp_m * 32 + mt * 16 + qr;
#pragma unroll
        for (int nt = 0; nt < 4; ++nt) {
            int cc = warp_n * 32 + nt * 8 + 2 * qc;
            *(float2*)&EhS[r * EH_STRIDE + cc] = make_float2(acc[mt][nt][0], acc[mt][nt][1]);
            *(float2*)&EhS[(r + 8) * EH_STRIDE + cc] = make_float2(acc[mt][nt][2], acc[mt][nt][3]);
        }
    }
    __syncthreads();

    // ---- edge phase: warp handles 8 edges; lane covers dims 4l..4l+3 ----
    const float4* Q4 = (const float4*)g_Q;
    const float4* KV4 = (const float4*)g_KV;
    float4* wV4 = (float4*)g_wV;
    int el0 = wid * 8;

    if (row0 + 64 <= E) {
        // fast path: software-pipelined, no bounds checks
        int dc = sDst[el0];
        int sc0 = sSrc[el0];
        float4 qv = Q4[(size_t)dc * 32 + lane];
        float4 kv = KV4[(size_t)sc0 * 64 + lane];
        float4 vv = KV4[(size_t)sc0 * 64 + 32 + lane];
#pragma unroll
        for (int i = 0; i < 8; ++i) {
            float4 qn, kn, vn;
            int dn = 0;
            if (i < 7) {
                int sn = sSrc[el0 + i + 1];
                dn = sDst[el0 + i + 1];
                qn = Q4[(size_t)dn * 32 + lane];
                kn = KV4[(size_t)sn * 64 + lane];
                vn = KV4[(size_t)sn * 64 + 32 + lane];
            }
            float4 ev = *(const float4*)&EhS[(el0 + i) * EH_STRIDE + lane * 4];
            float p = qv.x * kv.x * ev.x + qv.y * kv.y * ev.y +
                      qv.z * kv.z * ev.z + qv.w * kv.w * ev.w;
            p += __shfl_xor_sync(0xffffffffu, p, 1);
            p += __shfl_xor_sync(0xffffffffu, p, 2);
            p = fminf(5.0f, fmaxf(-5.0f, 0.25f * p));
            float sc = __expf(p);

            float4 m = make_float4(vv.x * sc, vv.y * sc, vv.z * sc, vv.w * sc);
            atomicAdd(wV4 + (size_t)dc * 32 + lane, m);
            if ((lane & 3) == 0) atomicAdd(&g_Z[dc * 8 + (lane >> 2)], sc);
            qv = qn; kv = kn; vv = vn; dc = dn;
        }
    } else {
        for (int i = 0; i < 8; ++i) {
            long e = row0 + el0 + i;
            if (e >= E) break;
            int s = sSrc[el0 + i];
            int d = sDst[el0 + i];
            float4 qv = Q4[(size_t)d * 32 + lane];
            float4 kv = KV4[(size_t)s * 64 + lane];
            float4 vv = KV4[(size_t)s * 64 + 32 + lane];
            float4 ev = *(const float4*)&EhS[(el0 + i) * EH_STRIDE + lane * 4];
            float p = qv.x * kv.x * ev.x + qv.y * kv.y * ev.y +
                      qv.z * kv.z * ev.z + qv.w * kv.w * ev.w;
            p += __shfl_xor_sync(0xffffffffu, p, 1);
            p += __shfl_xor_sync(0xffffffffu, p, 2);
            p = fminf(5.0f, fmaxf(-5.0f, 0.25f * p));
            float sc = __expf(p);
            float4 m = make_float4(vv.x * sc, vv.y * sc, vv.z * sc, vv.w * sc);
            atomicAdd(wV4 + (size_t)d * 32 + lane, m);
            if ((lane & 3) == 0) atomicAdd(&g_Z[d * 8 + (lane >> 2)], sc);
        }
    }
}

// -------- h = x + wV/(Z+eps) -> out; column stats (vectorized) --------
__global__ void __launch_bounds__(256) k_resid(const float* __restrict__ x,
                                               float* __restrict__ out, int N) {
    __shared__ float red[8 * 128];
    int tid = threadIdx.x;
    int c4 = tid & 31;          // float4 column group (cols 4*c4..4*c4+3)
    int w = tid >> 5;           // warp = row lane
    int h = c4 >> 2;            // head of this column group
    int r0 = blockIdx.x * 64;

    const float4* x4 = (const float4*)x;
    const float4* wv4 = (const float4*)g_wV;
    float4* o4 = (float4*)out;

    float4 s4 = make_float4(0.f, 0.f, 0.f, 0.f);
    float4 ss4 = make_float4(0.f, 0.f, 0.f, 0.f);
#pragma unroll
    for (int i = 0; i < 8; ++i) {
        int r = r0 + w + i * 8;
        if (r < N) {
            float zinv = 1.0f / (g_Z[r * 8 + h] + 1e-6f);
            size_t idx = (size_t)r * 32 + c4;
            float4 xv = x4[idx];
            float4 wv = wv4[idx];
            float4 hv = make_float4(xv.x + wv.x * zinv, xv.y + wv.y * zinv,
                                    xv.z + wv.z * zinv, xv.w + wv.w * zinv);
            o4[idx] = hv;
            s4.x += hv.x; s4.y += hv.y; s4.z += hv.z; s4.w += hv.w;
            ss4.x += hv.x * hv.x; ss4.y += hv.y * hv.y;
            ss4.z += hv.z * hv.z; ss4.w += hv.w * hv.w;
        }
    }
    *(float4*)&red[w * 128 + c4 * 4] = s4;
    __syncthreads();
    if (tid < 128) {
        float a = 0.f;
#pragma unroll
        for (int ww = 0; ww < 8; ++ww) a += red[ww * 128 + tid];
        atomicAdd(&g_cs[tid], a);
    }
    __syncthreads();
    *(float4*)&red[w * 128 + c4 * 4] = ss4;
    __syncthreads();
    if (tid < 128) {
        float a = 0.f;
#pragma unroll
        for (int ww = 0; ww < 8; ++ww) a += red[ww * 128 + tid];
        atomicAdd(&g_css[tid], a);
    }
}

// -------- batchnorm apply; stats finalized per-block in smem --------
__global__ void __launch_bounds__(256) k_final(float* __restrict__ out,
                                               const float* __restrict__ gamma,
                                               const float* __restrict__ beta,
                                               int N) {
    __shared__ float sm_scale[128];
    __shared__ float sm_shift[128];
    int tid = threadIdx.x;
    if (tid < 128) {
        float inv = 1.0f / (float)N;
        float mean = g_cs[tid] * inv;
        float var = g_css[tid] * inv - mean * mean;
        float rstd = rsqrtf(var + 1e-5f);
        float sc = rstd * gamma[tid];
        sm_scale[tid] = sc;
        sm_shift[tid] = beta[tid] - mean * sc;
    }
    __syncthreads();

    float4* o4 = (float4*)out;
    int total = N * 32;
#pragma unroll
    for (int j = 0; j < 4; ++j) {
        int idx = blockIdx.x * 1024 + j * 256 + tid;
        if (idx < total) {
            int c4 = (idx & 31) * 4;
            float4 v = o4[idx];
            float4 sc = *(float4*)&sm_scale[c4];
            float4 sh = *(float4*)&sm_shift[c4];
            v.x = v.x * sc.x + sh.x;
            v.y = v.y * sc.y + sh.y;
            v.z = v.z * sc.z + sh.z;
            v.w = v.w * sc.w + sh.w;
            o4[idx] = v;
        }
    }
}

extern "C" void kernel_launch(void* const* d_in, const int* in_sizes, int n_in,
                              void* d_out, int out_size) {
    const float* x     = (const float*)d_in[0];
    const float* eattr = (const float*)d_in[1];
    const float* WQ    = (const float*)d_in[2];
    const float* WK    = (const float*)d_in[3];
    const float* WV    = (const float*)d_in[4];
    const float* WE    = (const float*)d_in[5];
    const float* gamma = (const float*)d_in[6];
    const float* beta  = (const float*)d_in[7];
    const int*   ei    = (const int*)d_in[8];

    int N = in_sizes[0] / Dm;
    int E = in_sizes[1] / Dm;
    float* out = (float*)d_out;

    k_zero<<<(N * 32 + 255) / 256, 256>>>(N);

    dim3 gq((N + 127) / 128, 3);
    k_gemm_qkv<<<gq, 256>>>(x, WQ, WK, WV, N);

    k_eh_edge<<<(E + 63) / 64, 256>>>(eattr, WE, ei, E);

    k_resid<<<(N + 63) / 64, 256>>>(x, out, N);
    k_final<<<(N * 32 + 1023) / 1024, 256>>>(out, gamma, beta, N);
}

// round 6
// speedup vs baseline: 3.1007x; 1.0342x over previous
#include <cuda_runtime.h>
#include <math.h>
#include <stdint.h>

#define Dm 128
#define NMAX 50000

// -------- scratch (device globals; no allocation in kernel_launch) --------
__device__ float g_Q[NMAX * Dm];
__device__ float g_KV[(size_t)NMAX * 256];   // K in cols 0..127, V in cols 128..255
__device__ float g_wV[NMAX * Dm];
__device__ float g_Z[NMAX * 8];
__device__ float g_cs[Dm];
__device__ float g_css[Dm];

__global__ void __launch_bounds__(256) k_zero(int N) {
    int i = blockIdx.x * 256 + threadIdx.x;
    if (i < N * 32) ((float4*)g_wV)[i] = make_float4(0.f, 0.f, 0.f, 0.f);
    if (i < N * 2) ((float4*)g_Z)[i] = make_float4(0.f, 0.f, 0.f, 0.f);
    if (i < Dm) { g_cs[i] = 0.0f; g_css[i] = 0.0f; }
}

__device__ __forceinline__ float to_tf32(float x) {
    uint32_t u;
    asm("cvt.rna.tf32.f32 %0, %1;" : "=r"(u) : "f"(x));
    return __uint_as_float(u);
}

__device__ __forceinline__ void mma_tf32(float* c, const uint32_t* a, const uint32_t* b) {
    asm volatile(
        "mma.sync.aligned.m16n8k8.row.col.f32.tf32.tf32.f32 "
        "{%0,%1,%2,%3},{%4,%5,%6,%7},{%8,%9},{%0,%1,%2,%3};"
        : "+f"(c[0]), "+f"(c[1]), "+f"(c[2]), "+f"(c[3])
        : "r"(a[0]), "r"(a[1]), "r"(a[2]), "r"(a[3]), "r"(b[0]), "r"(b[1]));
}

// streamed float4 load (evict-first; protects L2 residency of Q/KV/wV)
__device__ __forceinline__ float4 ldcs4(const float4* p) {
    float4 v;
    asm volatile("ld.global.cs.v4.f32 {%0,%1,%2,%3}, [%4];"
                 : "=f"(v.x), "=f"(v.y), "=f"(v.z), "=f"(v.w) : "l"(p));
    return v;
}

#define AS_STRIDE 36
#define WS_STRIDE 136

// ============ QKV tf32 GEMM: 128x128 CTA tile, blockIdx.y selects matrix ============
__global__ void __launch_bounds__(256, 2) k_gemm_qkv(const float* __restrict__ A,
                                                     const float* __restrict__ WQ,
                                                     const float* __restrict__ WK,
                                                     const float* __restrict__ WV,
                                                     int M) {
    __shared__ float As[128 * AS_STRIDE];
    __shared__ float Ws[32 * WS_STRIDE];

    const float* W = (blockIdx.y == 0) ? WQ : (blockIdx.y == 1) ? WK : WV;
    float* C = (blockIdx.y == 0) ? g_Q : g_KV;
    int cst = (blockIdx.y == 0) ? 128 : 256;
    int coff = (blockIdx.y == 2) ? 128 : 0;

    int tid = threadIdx.x;
    int lane = tid & 31;
    int wid = tid >> 5;
    int warp_m = wid & 3;
    int warp_n = wid >> 2;
    int qr = lane >> 2;
    int qc = lane & 3;
    long row0 = (long)blockIdx.x * 128;

    float acc[2][8][4];
#pragma unroll
    for (int mt = 0; mt < 2; ++mt)
#pragma unroll
        for (int nt = 0; nt < 8; ++nt)
#pragma unroll
            for (int i = 0; i < 4; ++i) acc[mt][nt][i] = 0.0f;

    const float4* A4 = (const float4*)A;
    const float4* W4 = (const float4*)W;
    const uint32_t* Asu = (const uint32_t*)As;
    const uint32_t* Wsu = (const uint32_t*)Ws;

    for (int kc = 0; kc < 4; ++kc) {
        __syncthreads();
#pragma unroll
        for (int i = 0; i < 4; ++i) {
            int idx = tid + i * 256;
            int r = idx >> 3, c = idx & 7;
            float4 v = (row0 + r < M) ? A4[(row0 + r) * 32 + kc * 8 + c]
                                      : make_float4(0.f, 0.f, 0.f, 0.f);
            v.x = to_tf32(v.x); v.y = to_tf32(v.y);
            v.z = to_tf32(v.z); v.w = to_tf32(v.w);
            *(float4*)&As[r * AS_STRIDE + c * 4] = v;
        }
#pragma unroll
        for (int i = 0; i < 4; ++i) {
            int idx = tid + i * 256;
            int k = idx >> 5, c = idx & 31;
            float4 v = W4[(kc * 32 + k) * 32 + c];
            v.x = to_tf32(v.x); v.y = to_tf32(v.y);
            v.z = to_tf32(v.z); v.w = to_tf32(v.w);
            *(float4*)&Ws[k * WS_STRIDE + c * 4] = v;
        }
        __syncthreads();

#pragma unroll
        for (int ks = 0; ks < 4; ++ks) {
            int k0 = ks * 8;
            uint32_t af[2][4];
#pragma unroll
            for (int mt = 0; mt < 2; ++mt) {
                int rbase = (warp_m * 32 + mt * 16 + qr) * AS_STRIDE;
                af[mt][0] = Asu[rbase + k0 + qc];
                af[mt][1] = Asu[rbase + 8 * AS_STRIDE + k0 + qc];
                af[mt][2] = Asu[rbase + k0 + qc + 4];
                af[mt][3] = Asu[rbase + 8 * AS_STRIDE + k0 + qc + 4];
            }
            uint32_t bf[8][2];
#pragma unroll
            for (int nt = 0; nt < 8; ++nt) {
                int n = warp_n * 64 + nt * 8 + qr;
                bf[nt][0] = Wsu[(k0 + qc) * WS_STRIDE + n];
                bf[nt][1] = Wsu[(k0 + qc + 4) * WS_STRIDE + n];
            }
#pragma unroll
            for (int mt = 0; mt < 2; ++mt)
#pragma unroll
                for (int nt = 0; nt < 8; ++nt)
                    mma_tf32(acc[mt][nt], af[mt], bf[nt]);
        }
    }

#pragma unroll
    for (int mt = 0; mt < 2; ++mt) {
        long r = row0 + warp_m * 32 + mt * 16 + qr;
#pragma unroll
        for (int nt = 0; nt < 8; ++nt) {
            int cc = coff + warp_n * 64 + nt * 8 + 2 * qc;
            if (r < M)
                *(float2*)&C[(size_t)r * cst + cc] = make_float2(acc[mt][nt][0], acc[mt][nt][1]);
            if (r + 8 < M)
                *(float2*)&C[(size_t)(r + 8) * cst + cc] = make_float2(acc[mt][nt][2], acc[mt][nt][3]);
        }
    }
}

// ============ Fused Eh GEMM + edge attention ============
#define EH_STRIDE 132

__global__ void __launch_bounds__(256, 3) k_eh_edge(const float* __restrict__ A,
                                                    const float* __restrict__ W,
                                                    const int* __restrict__ ei, int E) {
    __shared__ float pool[64 * EH_STRIDE];  // 33.8 KB; unions staging + Eh tile
    __shared__ int sSrc[64];
    __shared__ int sDst[64];
    float* As = pool;
    float* Ws = pool + 64 * AS_STRIDE;
    float* EhS = pool;

    int tid = threadIdx.x;
    int lane = tid & 31;
    int wid = tid >> 5;
    int warp_m = wid & 1;
    int warp_n = wid >> 1;
    int qr = lane >> 2;
    int qc = lane & 3;
    long row0 = (long)blockIdx.x * 64;

    if (tid < 64)       sSrc[tid] = (row0 + tid < E) ? ei[row0 + tid] : 0;
    else if (tid < 128) sDst[tid - 64] = (row0 + tid - 64 < E) ? ei[E + row0 + tid - 64] : 0;

    float acc[2][4][4];
#pragma unroll
    for (int mt = 0; mt < 2; ++mt)
#pragma unroll
        for (int nt = 0; nt < 4; ++nt)
#pragma unroll
            for (int i = 0; i < 4; ++i) acc[mt][nt][i] = 0.0f;

    const float4* A4 = (const float4*)A;
    const float4* W4 = (const float4*)W;
    const uint32_t* Asu = (const uint32_t*)As;
    const uint32_t* Wsu = (const uint32_t*)Ws;

    for (int kc = 0; kc < 4; ++kc) {
        __syncthreads();
#pragma unroll
        for (int i = 0; i < 2; ++i) {
            int idx = tid + i * 256;
            int r = idx >> 3, c = idx & 7;
            float4 v = (row0 + r < E) ? ldcs4(&A4[(row0 + r) * 32 + kc * 8 + c])
                                      : make_float4(0.f, 0.f, 0.f, 0.f);
            v.x = to_tf32(v.x); v.y = to_tf32(v.y);
            v.z = to_tf32(v.z); v.w = to_tf32(v.w);
            *(float4*)&As[r * AS_STRIDE + c * 4] = v;
        }
#pragma unroll
        for (int i = 0; i < 4; ++i) {
            int idx = tid + i * 256;
            int k = idx >> 5, c = idx & 31;
            float4 v = W4[(kc * 32 + k) * 32 + c];
            v.x = to_tf32(v.x); v.y = to_tf32(v.y);
            v.z = to_tf32(v.z); v.w = to_tf32(v.w);
            *(float4*)&Ws[k * WS_STRIDE + c * 4] = v;
        }
        __syncthreads();

#pragma unroll
        for (int ks = 0; ks < 4; ++ks) {
            int k0 = ks * 8;
            uint32_t af[2][4];
#pragma unroll
            for (int mt = 0; mt < 2; ++mt) {
                int rbase = (warp_m * 32 + mt * 16 + qr) * AS_STRIDE;
                af[mt][0] = Asu[rbase + k0 + qc];
                af[mt][1] = Asu[rbase + 8 * AS_STRIDE + k0 + qc];
                af[mt][2] = Asu[rbase + k0 + qc + 4];
                af[mt][3] = Asu[rbase + 8 * AS_STRIDE + k0 + qc + 4];
            }
            uint32_t bf[4][2];
#pragma unroll
            for (int nt = 0; nt < 4; ++nt) {
                int n = warp_n * 32 + nt * 8 + qr;
                bf[nt][0] = Wsu[(k0 + qc) * WS_STRIDE + n];
                bf[nt][1] = Wsu[(k0 + qc + 4) * WS_STRIDE + n];
            }
#pragma unroll
            for (int mt = 0; mt < 2; ++mt)
#pragma unroll
                for (int nt = 0; nt < 4; ++nt)
                    mma_tf32(acc[mt][nt], af[mt], bf[nt]);
        }
    }

    __syncthreads();  // staging dead; overwrite with Eh tile

#pragma unroll
    for (int mt = 0; mt < 2; ++mt) {
        int r = warp_m * 32 + mt * 16 + qr;
#pragma unroll
        for (int nt = 0; nt < 4; ++nt) {
            int cc = warp_n * 32 + nt * 8 + 2 * qc;
            *(float2*)&EhS[r * EH_STRIDE + cc] = make_float2(acc[mt][nt][0], acc[mt][nt][1]);
            *(float2*)&EhS[(r + 8) * EH_STRIDE + cc] = make_float2(acc[mt][nt][2], acc[mt][nt][3]);
        }
    }
    __syncthreads();

    // ---- edge phase: warp handles 8 edges, depth-2 pipelined ----
    const float4* Q4 = (const float4*)g_Q;
    const float4* KV4 = (const float4*)g_KV;
    float4* wV4 = (float4*)g_wV;
    int el0 = wid * 8;

    if (row0 + 64 <= E) {
        int d[3], sN[3];
        float4 q[3], k[3], v[3];
        // prime stages 0 and 1
#pragma unroll
        for (int j = 0; j < 2; ++j) {
            sN[j] = sSrc[el0 + j];
            d[j] = sDst[el0 + j];
            q[j] = Q4[(size_t)d[j] * 32 + lane];
            k[j] = KV4[(size_t)sN[j] * 64 + lane];
            v[j] = KV4[(size_t)sN[j] * 64 + 32 + lane];
        }
#pragma unroll
        for (int i = 0; i < 8; ++i) {
            int st = i % 3;
            int pf = (i + 2) % 3;
            if (i < 6) {
                int sn = sSrc[el0 + i + 2];
                int dn = sDst[el0 + i + 2];
                sN[pf] = sn; d[pf] = dn;
                q[pf] = Q4[(size_t)dn * 32 + lane];
                k[pf] = KV4[(size_t)sn * 64 + lane];
                v[pf] = KV4[(size_t)sn * 64 + 32 + lane];
            }
            float4 ev = *(const float4*)&EhS[(el0 + i) * EH_STRIDE + lane * 4];
            float4 qv = q[st], kv = k[st], vv = v[st];
            float p = qv.x * kv.x * ev.x + qv.y * kv.y * ev.y +
                      qv.z * kv.z * ev.z + qv.w * kv.w * ev.w;
            p += __shfl_xor_sync(0xffffffffu, p, 1);
            p += __shfl_xor_sync(0xffffffffu, p, 2);
            p = fminf(5.0f, fmaxf(-5.0f, 0.25f * p));
            float sc = __expf(p);

            int dc = d[st];
            if ((lane & 3) == 0) atomicAdd(&g_Z[dc * 8 + (lane >> 2)], sc);
            float4 m = make_float4(vv.x * sc, vv.y * sc, vv.z * sc, vv.w * sc);
            atomicAdd(wV4 + (size_t)dc * 32 + lane, m);
        }
    } else {
        for (int i = 0; i < 8; ++i) {
            long e = row0 + el0 + i;
            if (e >= E) break;
            int s = sSrc[el0 + i];
            int dd = sDst[el0 + i];
            float4 qv = Q4[(size_t)dd * 32 + lane];
            float4 kv = KV4[(size_t)s * 64 + lane];
            float4 vv = KV4[(size_t)s * 64 + 32 + lane];
            float4 ev = *(const float4*)&EhS[(el0 + i) * EH_STRIDE + lane * 4];
            float p = qv.x * kv.x * ev.x + qv.y * kv.y * ev.y +
                      qv.z * kv.z * ev.z + qv.w * kv.w * ev.w;
            p += __shfl_xor_sync(0xffffffffu, p, 1);
            p += __shfl_xor_sync(0xffffffffu, p, 2);
            p = fminf(5.0f, fmaxf(-5.0f, 0.25f * p));
            float sc = __expf(p);
            if ((lane & 3) == 0) atomicAdd(&g_Z[dd * 8 + (lane >> 2)], sc);
            float4 m = make_float4(vv.x * sc, vv.y * sc, vv.z * sc, vv.w * sc);
            atomicAdd(wV4 + (size_t)dd * 32 + lane, m);
        }
    }
}

// -------- h = x + wV/(Z+eps) -> out; column stats (vectorized) --------
__global__ void __launch_bounds__(256) k_resid(const float* __restrict__ x,
                                               float* __restrict__ out, int N) {
    __shared__ float red[8 * 128];
    int tid = threadIdx.x;
    int c4 = tid & 31;
    int w = tid >> 5;
    int h = c4 >> 2;
    int r0 = blockIdx.x * 64;

    const float4* x4 = (const float4*)x;
    const float4* wv4 = (const float4*)g_wV;
    float4* o4 = (float4*)out;

    float4 s4 = make_float4(0.f, 0.f, 0.f, 0.f);
    float4 ss4 = make_float4(0.f, 0.f, 0.f, 0.f);
#pragma unroll
    for (int i = 0; i < 8; ++i) {
        int r = r0 + w + i * 8;
        if (r < N) {
            float zinv = 1.0f / (g_Z[r * 8 + h] + 1e-6f);
            size_t idx = (size_t)r * 32 + c4;
            float4 xv = x4[idx];
            float4 wv = wv4[idx];
            float4 hv = make_float4(xv.x + wv.x * zinv, xv.y + wv.y * zinv,
                                    xv.z + wv.z * zinv, xv.w + wv.w * zinv);
            o4[idx] = hv;
            s4.x += hv.x; s4.y += hv.y; s4.z += hv.z; s4.w += hv.w;
            ss4.x += hv.x * hv.x; ss4.y += hv.y * hv.y;
            ss4.z += hv.z * hv.z; ss4.w += hv.w * hv.w;
        }
    }
    *(float4*)&red[w * 128 + c4 * 4] = s4;
    __syncthreads();
    if (tid < 128) {
        float a = 0.f;
#pragma unroll
        for (int ww = 0; ww < 8; ++ww) a += red[ww * 128 + tid];
        atomicAdd(&g_cs[tid], a);
    }
    __syncthreads();
    *(float4*)&red[w * 128 + c4 * 4] = ss4;
    __syncthreads();
    if (tid < 128) {
        float a = 0.f;
#pragma unroll
        for (int ww = 0; ww < 8; ++ww) a += red[ww * 128 + tid];
        atomicAdd(&g_css[tid], a);
    }
}

// -------- batchnorm apply; stats finalized per-block in smem --------
__global__ void __launch_bounds__(256) k_final(float* __restrict__ out,
                                               const float* __restrict__ gamma,
                                               const float* __restrict__ beta,
                                               int N) {
    __shared__ float sm_scale[128];
    __shared__ float sm_shift[128];
    int tid = threadIdx.x;
    if (tid < 128) {
        float inv = 1.0f / (float)N;
        float mean = g_cs[tid] * inv;
        float var = g_css[tid] * inv - mean * mean;
        float rstd = rsqrtf(var + 1e-5f);
        float sc = rstd * gamma[tid];
        sm_scale[tid] = sc;
        sm_shift[tid] = beta[tid] - mean * sc;
    }
    __syncthreads();

    float4* o4 = (float4*)out;
    int total = N * 32;
#pragma unroll
    for (int j = 0; j < 4; ++j) {
        int idx = blockIdx.x * 1024 + j * 256 + tid;
        if (idx < total) {
            int c4 = (idx & 31) * 4;
            float4 v = o4[idx];
            float4 sc = *(float4*)&sm_scale[c4];
            float4 sh = *(float4*)&sm_shift[c4];
            v.x = v.x * sc.x + sh.x;
            v.y = v.y * sc.y + sh.y;
            v.z = v.z * sc.z + sh.z;
            v.w = v.w * sc.w + sh.w;
            o4[idx] = v;
        }
    }
}

extern "C" void kernel_launch(void* const* d_in, const int* in_sizes, int n_in,
                              void* d_out, int out_size) {
    const float* x     = (const float*)d_in[0];
    const float* eattr = (const float*)d_in[1];
    const float* WQ    = (const float*)d_in[2];
    const float* WK    = (const float*)d_in[3];
    const float* WV    = (const float*)d_in[4];
    const float* WE    = (const float*)d_in[5];
    const float* gamma = (const float*)d_in[6];
    const float* beta  = (const float*)d_in[7];
    const int*   ei    = (const int*)d_in[8];

    int N = in_sizes[0] / Dm;
    int E = in_sizes[1] / Dm;
    float* out = (float*)d_out;

    k_zero<<<(N * 32 + 255) / 256, 256>>>(N);

    dim3 gq((N + 127) / 128, 3);
    k_gemm_qkv<<<gq, 256>>>(x, WQ, WK, WV, N);

    k_eh_edge<<<(E + 63) / 64, 256>>>(eattr, WE, ei, E);

    k_resid<<<(N + 63) / 64, 256>>>(x, out, N);
    k_final<<<(N * 32 + 1023) / 1024, 256>>>(out, gamma, beta, N);
}